// round 1
// baseline (speedup 1.0000x reference)
#include <cuda_runtime.h>

#define SK_N 512
#define SK_ITERS 21
#define SK_THREADS 512

// One CTA per batch matrix. State = u[512], v[512] in SMEM.
//   U_i <- LSE_j(s_ij - V_j)   (row pass, register-resident two-phase LSE)
//   V_j <- LSE_i(s_ij - U_i)   (col pass, online LSE, ballot-gated exp)
//   out = exp(s - U - V)
__global__ void __launch_bounds__(SK_THREADS, 2)
sinkhorn_kernel(const float* __restrict__ x, float* __restrict__ out)
{
    const int b = blockIdx.x;
    const float* __restrict__ X = x + (size_t)b * SK_N * SK_N;
    float* __restrict__ O = out + (size_t)b * SK_N * SK_N;

    __shared__ float u_s[SK_N];
    __shared__ float v_s[SK_N];

    const int tid  = threadIdx.x;
    const int lane = tid & 31;
    const int wid  = tid >> 5;   // 0..15
    const unsigned FULL = 0xffffffffu;

    v_s[tid] = 0.0f;
    __syncthreads();

    for (int it = 0; it < SK_ITERS; ++it) {
        // ---------------- U update: u_i = LSE_j(x_ij*100 - v_j) ----------------
        // One warp per row; 16 elements per lane held in registers so the
        // max pass and the sum pass share a single global read.
        for (int r = wid; r < SK_N; r += 16) {
            const float4* xr = reinterpret_cast<const float4*>(X + (size_t)r * SK_N);
            const float4* vr = reinterpret_cast<const float4*>(v_s);
            float z[16];
            float m = -3.4e38f;
            #pragma unroll
            for (int k = 0; k < 4; ++k) {
                float4 xv = xr[lane + 32 * k];
                float4 vv = vr[lane + 32 * k];
                z[4 * k + 0] = xv.x * 100.0f - vv.x;
                z[4 * k + 1] = xv.y * 100.0f - vv.y;
                z[4 * k + 2] = xv.z * 100.0f - vv.z;
                z[4 * k + 3] = xv.w * 100.0f - vv.w;
            }
            #pragma unroll
            for (int e = 0; e < 16; ++e) m = fmaxf(m, z[e]);
            #pragma unroll
            for (int off = 16; off > 0; off >>= 1)
                m = fmaxf(m, __shfl_xor_sync(FULL, m, off));
            float ssum = 0.0f;
            #pragma unroll
            for (int e = 0; e < 16; ++e) ssum += __expf(z[e] - m);
            #pragma unroll
            for (int off = 16; off > 0; off >>= 1)
                ssum += __shfl_xor_sync(FULL, ssum, off);
            if (lane == 0) u_s[r] = m + __logf(ssum);
        }
        __syncthreads();

        // ---------------- V update: v_j = LSE_i(x_ij*100 - u_i) ----------------
        // Thread <-> column (perfectly coalesced row-at-a-time loads).
        // Online LSE; the update body is skipped when no lane in the warp has a
        // term within 25 of its running max (exp of those terms is < 1.4e-11
        // relative to the sum, far below the 1e-3 tolerance).
        {
            const int c = tid;
            float m = -3.4e38f;
            float ssum = 0.0f;
            for (int r0 = 0; r0 < SK_N; r0 += 8) {
                float xv[8];
                #pragma unroll
                for (int k = 0; k < 8; ++k)
                    xv[k] = X[(size_t)(r0 + k) * SK_N + c];
                #pragma unroll
                for (int k = 0; k < 8; ++k) {
                    float z = xv[k] * 100.0f - u_s[r0 + k];
                    if (__ballot_sync(FULL, z > m - 25.0f)) {
                        float mn = fmaxf(m, z);
                        ssum = ssum * __expf(m - mn) + __expf(z - mn);
                        m = mn;
                    }
                }
            }
            v_s[c] = m + __logf(ssum);
        }
        __syncthreads();
    }

    // ---------------- Output: exp(x*100 - u_i - v_j) ----------------
    for (int r = wid; r < SK_N; r += 16) {
        const float ur = u_s[r];
        const float4* xr = reinterpret_cast<const float4*>(X + (size_t)r * SK_N);
        const float4* vr = reinterpret_cast<const float4*>(v_s);
        float4* orow = reinterpret_cast<float4*>(O + (size_t)r * SK_N);
        #pragma unroll
        for (int k = 0; k < 4; ++k) {
            float4 xv = xr[lane + 32 * k];
            float4 vv = vr[lane + 32 * k];
            float4 o;
            o.x = __expf(xv.x * 100.0f - ur - vv.x);
            o.y = __expf(xv.y * 100.0f - ur - vv.y);
            o.z = __expf(xv.z * 100.0f - ur - vv.z);
            o.w = __expf(xv.w * 100.0f - ur - vv.w);
            orow[lane + 32 * k] = o;
        }
    }
}

extern "C" void kernel_launch(void* const* d_in, const int* in_sizes, int n_in,
                              void* d_out, int out_size)
{
    const float* x = (const float*)d_in[0];
    float* out = (float*)d_out;
    const int batches = in_sizes[0] / (SK_N * SK_N);
    sinkhorn_kernel<<<batches, SK_THREADS>>>(x, out);
}